// round 16
// baseline (speedup 1.0000x reference)
#include <cuda_runtime.h>
#include <cstddef>

typedef unsigned long long u64;

#define DIM   16384
#define OUT_N 1000
#define BLK   256

// bank bits 2-4 ^= addr bits 10-12; bits 0,1 intact (64/128-bit safe). Linear over GF(2).
__device__ __forceinline__ unsigned swz(unsigned a){ return a ^ (((a>>10)&7u)<<2); }

__device__ __forceinline__ u64 fma2(u64 a,u64 b,u64 c){ u64 d; asm("fma.rn.f32x2 %0,%1,%2,%3;":"=l"(d):"l"(a),"l"(b),"l"(c)); return d; }
__device__ __forceinline__ u64 pk2(float lo,float hi){ u64 r; asm("mov.b64 %0,{%1,%2};":"=l"(r):"f"(lo),"f"(hi)); return r; }
__device__ __forceinline__ void unpk2(u64 v,float&lo,float&hi){ asm("mov.b64 {%0,%1},%2;":"=f"(lo),"=f"(hi):"l"(v)); }
__device__ __forceinline__ u64 dup2(float x){ return pk2(x,x); }
__device__ __forceinline__ u64 neg2(u64 v){ return v ^ 0x8000000080000000ULL; }   // 2x LOP3, alu pipe

// Packed tangent-form fused CZ + RY(high PH) + RY(low PL) on 16 f32x2 amps.
// g = {t0, -t0, t1, -t1} (dup2'ed, in shared).
template<int PH,int PL>
__device__ __forceinline__ void gate2p(u64 q[16], const u64* __restrict__ g){
    const u64 t0 = g[0], nt0 = g[1], t1 = g[2], nt1 = g[3];
#pragma unroll
    for(int k=0;k<16;++k) if(!((k>>PH)&1) && !((k>>PL)&1)){
        const int k01=k|(1<<PL), k10=k|(1<<PH), k11=k10|(1<<PL);
        u64 y00 = fma2(nt0, q[k10], q[k]);    //  a00 - t0*a10
        u64 y10 = fma2(t0,  q[k],   q[k10]);  //  t0*a00 + a10
        u64 y01 = fma2(t0,  q[k11], q[k01]);  //  a01 + t0*a11   (CZ fold)
        u64 z11 = fma2(nt0, q[k01], q[k11]);  //  a11 - t0*a01 = -y11
        q[k]   = fma2(nt1, y01, y00);         //  y00 - t1*y01
        q[k01] = fma2(t1,  y00, y01);         //  t1*y00 + y01
        q[k10] = fma2(t1,  z11, y10);         //  y10 - t1*y11
        q[k11] = neg2(fma2(nt1, y10, z11));   //  t1*y10 + y11
    }
}
// Packed bias RY on bit P; bb = {t, -t}.
template<int P>
__device__ __forceinline__ void bias1p(u64 q[16], const u64* __restrict__ bb){
    const u64 t = bb[0], nt = bb[1];
#pragma unroll
    for(int k=0;k<16;++k) if(!((k>>P)&1)){
        const int k1 = k|(1<<P);
        u64 y0 = fma2(nt, q[k1], q[k]);
        q[k1]  = fma2(t,  q[k],  q[k1]);
        q[k]   = y0;
    }
}

// 64-bit tile ld/st: spectator = amp bit 0 (pb even).
template<int B3,int B2,int B1,int B0>
__device__ __forceinline__ void ldt(const float* __restrict__ S, unsigned pb, u64 q[16]){
#pragma unroll
    for(int k=0;k<16;++k){
        const unsigned off = swz((unsigned)((((k>>3)&1)<<B3)|(((k>>2)&1)<<B2)|(((k>>1)&1)<<B1)|((k&1)<<B0)));
        q[k] = *(const u64*)(S + (pb ^ off));
    }
}
template<int B3,int B2,int B1,int B0>
__device__ __forceinline__ void stt(float* __restrict__ S, unsigned pb, const u64 q[16]){
#pragma unroll
    for(int k=0;k<16;++k){
        const unsigned off = swz((unsigned)((((k>>3)&1)<<B3)|(((k>>2)&1)<<B2)|(((k>>1)&1)<<B1)|((k&1)<<B0)));
        *(u64*)(S + (pb ^ off)) = q[k];
    }
}

__global__ __launch_bounds__(BLK, 3)
void qnn_kernel(const float* __restrict__ input,
                const float* __restrict__ weights,   // (2,13,2)
                const float* __restrict__ bias,      // (14,)
                float* __restrict__ out)             // (B,1000)
{
    extern __shared__ float S[];                     // DIM floats, swizzled layout
    __shared__ u64   Gt4[26][4];                     // packed {t0,-t0,t1,-t1}
    __shared__ u64   Bt2[14][2];                     // packed bias {t,-t}, by BIT position
    __shared__ float Cg[26], Cb[14];                 // deferred cosines
    __shared__ float warpsum[BLK/32];
    __shared__ float s_inv;

    const int tid = threadIdx.x;
    const int b   = blockIdx.x;

    // id 0-6: L1 even (i=2*id) -> bits(13-i,12-i); 7-12: L1 odd; 13-19: L2 even; 20-25: L2 odd
    if (tid < 26) {
        int l, i;
        if (tid < 7)       { l=0; i=2*tid; }
        else if (tid < 13) { l=0; i=2*(tid-7)+1; }
        else if (tid < 20) { l=1; i=2*(tid-13); }
        else               { l=1; i=2*(tid-20)+1; }
        float c0,s0,c1,s1;
        sincosf(0.5f*weights[l*26+i*2+0], &s0, &c0);
        sincosf(0.5f*weights[l*26+i*2+1], &s1, &c1);
        float t0 = s0/c0, t1 = s1/c1;
        Gt4[tid][0]=dup2(t0); Gt4[tid][1]=dup2(-t0);
        Gt4[tid][2]=dup2(t1); Gt4[tid][3]=dup2(-t1);
        Cg[tid] = c0*c1;
    }
    if (tid < 14) {                                  // bit w holds qubit 13-w
        float c,s; sincosf(0.5f*bias[13-tid], &s, &c);
        float t = s/c;
        Bt2[tid][0]=dup2(t); Bt2[tid][1]=dup2(-t);
        Cb[tid] = c;
    }
    __syncthreads();

    // warp 0: product of all 66 cosines
    float scl = 1.f;
    if (tid < 32) {
        if (tid < 26) scl *= Cg[tid];
        if (tid < 14) scl *= Cb[tid];
#pragma unroll
        for (int o=16;o;o>>=1) scl *= __shfl_xor_sync(~0u, scl, o);
    }

    u64 q[16];
    u64 acc2 = 0;                                    // packed {0.f,0.f}

    // ===== S1 (gmem -> regs -> smem): tile(13,12,11,10), spec bit 0, base idx<<1
    //   bias13..10, E1(13,12), E1(11,10), O1(12,11), E2(13,12)
    const float* row = input + (size_t)b * DIM;
#pragma unroll 1
    for (int it=0; it<2; ++it){
        const unsigned idx  = (unsigned)tid | ((unsigned)it<<8);  // [0,512)
        const unsigned base = idx << 1;
#pragma unroll
        for (int k=0;k<16;++k){
            q[k] = *(const u64*)(row + (base | ((unsigned)k<<10)));
            acc2 = fma2(q[k], q[k], acc2);
        }
        bias1p<3>(q,Bt2[13]); bias1p<2>(q,Bt2[12]); bias1p<1>(q,Bt2[11]); bias1p<0>(q,Bt2[10]);
        gate2p<3,2>(q,Gt4[0]); gate2p<1,0>(q,Gt4[1]); gate2p<2,1>(q,Gt4[7]); gate2p<3,2>(q,Gt4[13]);
        stt<13,12,11,10>(S, swz(base), q);
    }
    {
        float a0,a1; unpk2(acc2,a0,a1);
        float acc = a0 + a1;
#pragma unroll
        for (int o=16;o;o>>=1) acc += __shfl_xor_sync(~0u, acc, o);
        if ((tid&31)==0) warpsum[tid>>5] = acc;
    }
    __syncthreads();                                 // orders S1 stores before S2 loads
    if (tid < BLK/32){
        float v = warpsum[tid];
#pragma unroll
        for (int o=(BLK/32)/2;o;o>>=1) v += __shfl_xor_sync(0xffu, v, o);
        if (!tid) s_inv = (scl*scl)/v;               // sc^2 / ||x||^2
    }

    // ===== S2: tile(9,8,7,6), spec 0, base {1-5,10-13}: bias9..6, E1(9,8), E1(7,6), O1(8,7)
#pragma unroll 1
    for (int it=0; it<2; ++it){
        const unsigned idx = (unsigned)tid | ((unsigned)it<<8);
        const unsigned pb  = swz(((idx&31u)<<1) | ((idx>>5)<<10));
        ldt<9,8,7,6>(S, pb, q);
        bias1p<3>(q,Bt2[9]); bias1p<2>(q,Bt2[8]); bias1p<1>(q,Bt2[7]); bias1p<0>(q,Bt2[6]);
        gate2p<3,2>(q,Gt4[2]); gate2p<1,0>(q,Gt4[3]); gate2p<2,1>(q,Gt4[9]);
        stt<9,8,7,6>(S, pb, q);
    }
    __syncthreads();

    // ===== S3: tile(5,4,3,2), spec 0, base {1,6-13}: bias5..2, E1(5,4), E1(3,2), O1(4,3)
#pragma unroll 1
    for (int it=0; it<2; ++it){
        const unsigned idx = (unsigned)tid | ((unsigned)it<<8);
        const unsigned pb  = swz(((idx&1u)<<1) | (((idx>>1)&7u)<<10)
                               | (((idx>>4)&15u)<<6) | ((idx>>8)<<13));
        ldt<5,4,3,2>(S, pb, q);
        bias1p<3>(q,Bt2[5]); bias1p<2>(q,Bt2[4]); bias1p<1>(q,Bt2[3]); bias1p<0>(q,Bt2[2]);
        gate2p<3,2>(q,Gt4[4]);  gate2p<1,0>(q,Gt4[5]);  gate2p<2,1>(q,Gt4[11]);
        stt<5,4,3,2>(S, pb, q);
    }
    __syncthreads();

    // ===== S4: tile(3,2,1,0) contiguous (float4 x2), spec bit 4, base {5-13}
    //   bias1,0, E1(1,0), O1(2,1), E2(1,0)
#pragma unroll 1
    for (int it=0; it<2; ++it){
        const unsigned idx  = (unsigned)tid | ((unsigned)it<<8);
        const unsigned base = ((idx&7u)<<10) | (((idx>>3)&31u)<<5) | ((idx>>8)<<13);
        const unsigned pb   = swz(base);             // bits 0,1 of pb are 0
#pragma unroll
        for (int m=0;m<4;++m){
            float4 v = *(const float4*)(S + (pb ^ (unsigned)(m<<2)));
            float4 w = *(const float4*)(S + (pb ^ (unsigned)((m<<2)|16)));
            q[4*m]   = pk2(v.x,w.x); q[4*m+1] = pk2(v.y,w.y);
            q[4*m+2] = pk2(v.z,w.z); q[4*m+3] = pk2(v.w,w.w);
        }
        bias1p<1>(q,Bt2[1]); bias1p<0>(q,Bt2[0]);
        gate2p<1,0>(q,Gt4[6]); gate2p<2,1>(q,Gt4[12]); gate2p<1,0>(q,Gt4[19]);
#pragma unroll
        for (int m=0;m<4;++m){
            float ax,bx,ay,by,az,bz,aw,bw;
            unpk2(q[4*m],ax,bx); unpk2(q[4*m+1],ay,by);
            unpk2(q[4*m+2],az,bz); unpk2(q[4*m+3],aw,bw);
            *(float4*)(S + (pb ^ (unsigned)(m<<2)))      = make_float4(ax,ay,az,aw);
            *(float4*)(S + (pb ^ (unsigned)((m<<2)|16))) = make_float4(bx,by,bz,bw);
        }
    }
    __syncthreads();

    // ===== S5: tile(11,10,9,8), spec 0, base {1-7,12,13}: O1(10,9), E2(11,10), E2(9,8), O2(10,9)
#pragma unroll 1
    for (int it=0; it<2; ++it){
        const unsigned idx = (unsigned)tid | ((unsigned)it<<8);
        const unsigned pb  = swz(((idx&127u)<<1) | ((idx>>7)<<12));
        ldt<11,10,9,8>(S, pb, q);
        gate2p<2,1>(q,Gt4[8]);  gate2p<3,2>(q,Gt4[14]);
        gate2p<1,0>(q,Gt4[15]); gate2p<2,1>(q,Gt4[21]);
        stt<11,10,9,8>(S, pb, q);
    }
    __syncthreads();

    // ===== S6: tile(12,11,6,5), spec 0, base {1-4,7-10,13}: O1(6,5), O2(12,11)
#pragma unroll 1
    for (int it=0; it<2; ++it){
        const unsigned idx = (unsigned)tid | ((unsigned)it<<8);
        const unsigned pb  = swz(((idx&15u)<<1) | (((idx>>4)&15u)<<7) | ((idx>>8)<<13));
        ldt<12,11,6,5>(S, pb, q);
        gate2p<1,0>(q,Gt4[10]); gate2p<3,2>(q,Gt4[20]);
        stt<12,11,6,5>(S, pb, q);
    }
    __syncthreads();

    // ===== S7: tile(8,7,6,5), spec 0, base {1-4,9-13}: E2(7,6), O2(8,7)
#pragma unroll 1
    for (int it=0; it<2; ++it){
        const unsigned idx = (unsigned)tid | ((unsigned)it<<8);
        const unsigned pb  = swz(((idx&15u)<<1) | ((idx>>4)<<9));
        ldt<8,7,6,5>(S, pb, q);
        gate2p<2,1>(q,Gt4[16]); gate2p<3,2>(q,Gt4[22]);
        stt<8,7,6,5>(S, pb, q);
    }
    __syncthreads();

    // ===== S8: tile(5,4,3,2), spec 0 (same base map as S3): E2(5,4), E2(3,2), O2(4,3)
#pragma unroll 1
    for (int it=0; it<2; ++it){
        const unsigned idx = (unsigned)tid | ((unsigned)it<<8);
        const unsigned pb  = swz(((idx&1u)<<1) | (((idx>>1)&7u)<<10)
                               | (((idx>>4)&15u)<<6) | ((idx>>8)<<13));
        ldt<5,4,3,2>(S, pb, q);
        gate2p<3,2>(q,Gt4[17]); gate2p<1,0>(q,Gt4[18]); gate2p<2,1>(q,Gt4[24]);
        stt<5,4,3,2>(S, pb, q);
    }
    __syncthreads();

    // ===== S9: tile(6,5,2,1), spec 0, base {3,4,7-13}: O2(6,5), O2(2,1)
    //   (2-way bank conflict inherent; accepted)
#pragma unroll 1
    for (int it=0; it<2; ++it){
        const unsigned idx  = (unsigned)tid | ((unsigned)it<<8);
        const unsigned base = ((idx&1u)<<3) | (((idx>>1)&1u)<<4)
                            | (((idx>>2)&1u)<<10) | (((idx>>3)&1u)<<11)
                            | (((idx>>4)&7u)<<7) | ((idx>>7)<<12);
        const unsigned pb   = swz(base);
        ldt<6,5,2,1>(S, pb, q);
        gate2p<3,2>(q,Gt4[23]); gate2p<1,0>(q,Gt4[25]);
        stt<6,5,2,1>(S, pb, q);
    }
    __syncthreads();

    // ---- epilogue: probs of last OUT_N states, scaled by sc^2/||x||^2 ----
    const float inv = s_inv;
    float* orow = out + (size_t)b*OUT_N;
    for (int j=tid; j<OUT_N; j+=BLK){
        float a = S[swz((unsigned)(DIM-OUT_N+j))];
        orow[j] = a*a*inv;
    }
}

extern "C" void kernel_launch(void* const* d_in, const int* in_sizes, int n_in,
                              void* d_out, int out_size)
{
    const float* input   = (const float*)d_in[0];   // (B,16384) f32
    const float* weights = (const float*)d_in[1];   // (2,13,2)  f32
    const float* bias    = (const float*)d_in[2];   // (14,)     f32
    float* out = (float*)d_out;                     // (B,1000)  f32

    const int B = in_sizes[0] / DIM;                // 512

    cudaFuncSetAttribute(qnn_kernel,
                         cudaFuncAttributeMaxDynamicSharedMemorySize,
                         DIM * (int)sizeof(float));

    qnn_kernel<<<B, BLK, DIM * sizeof(float)>>>(input, weights, bias, out);
}